// round 13
// baseline (speedup 1.0000x reference)
#include <cuda_runtime.h>
#include <cuda_fp16.h>
#include <cstdint>

// Problem dims (fixed by the dataset)
#define M_DIM 8192
#define K_DIM 4096
#define N_DIM 11008

// GEMM tiling
#define BM 128
#define BN 128
#define BK 64                 // fp16 elems per k-tile = 128 bytes per row
#define STAGES 3
#define KTILES (K_DIM / BK)   // 64
#define NTHREADS 256

#define ROW_BYTES 128                      // 64 halves; XOR-swizzled chunks, no pad
#define A_STAGE_BYTES (BM * ROW_BYTES)     // 16384
#define B_STAGE_BYTES (BN * ROW_BYTES)     // 16384
#define STAGE_BYTES (A_STAGE_BYTES + B_STAGE_BYTES)
#define SMEM_BYTES (STAGES * STAGE_BYTES)  // 98304 -> 2 CTAs/SM

// Scratch (device globals: allocation-free rule)
__device__ __align__(128) __half g_Ah [(size_t)M_DIM * K_DIM];  // 64 MB quantized x as fp16 ints
__device__ __align__(128) __half g_Bth[(size_t)N_DIM * K_DIM];  // 90 MB W^T [N,K] fp16

// ---------------- PTX helpers (baseline ISA only) ----------------
__device__ __forceinline__ uint32_t smem_u32(const void* p) {
    uint32_t a;
    asm("{ .reg .u64 t; cvta.to.shared.u64 t, %1; cvt.u32.u64 %0, t; }" : "=r"(a) : "l"(p));
    return a;
}
__device__ __forceinline__ void cp_async16(uint32_t dst, const void* src) {
    asm volatile("cp.async.cg.shared.global [%0], [%1], 16;" :: "r"(dst), "l"(src));
}
#define CP_COMMIT() asm volatile("cp.async.commit_group;" ::: "memory")
#define CP_WAIT(n)  asm volatile("cp.async.wait_group %0;" :: "n"(n) : "memory")

#define LDMX4(r, addr) \
    asm volatile("ldmatrix.sync.aligned.m8n8.x4.shared.b16 {%0,%1,%2,%3}, [%4];" \
        : "=r"((r)[0]), "=r"((r)[1]), "=r"((r)[2]), "=r"((r)[3]) : "r"(addr))

// m16n8k16 fp16 inputs, fp32 accumulate — C=D in place.
#define MMA_F16(d, a, b0, b1) \
    asm volatile("mma.sync.aligned.m16n8k16.row.col.f32.f16.f16.f32 " \
        "{%0,%1,%2,%3}, {%4,%5,%6,%7}, {%8,%9}, {%0,%1,%2,%3};" \
        : "+f"((d)[0]), "+f"((d)[1]), "+f"((d)[2]), "+f"((d)[3]) \
        : "r"((a)[0]), "r"((a)[1]), "r"((a)[2]), "r"((a)[3]), "r"(b0), "r"(b1))

// -------- Fused pre-pass: quant (x -> fp16 ints) + transpose (W int32 -> Wt fp16) ----
// Blocks [0, QBLOCKS) quantize; blocks [QBLOCKS, QBLOCKS+TBLOCKS) transpose.
#define QBLOCKS ((M_DIM * K_DIM / 8) / 256)                 // 16384
#define TBX (N_DIM / 64)                                    // 172
#define TBLOCKS (TBX * (K_DIM / 64))                        // 11008

__global__ __launch_bounds__(256, 8)
void prep_kernel(const float* __restrict__ x, const int* __restrict__ w,
                 const float* __restrict__ iscale) {
    __shared__ __align__(16) __half tile[64][72];  // transpose staging (unused by quant blocks)
    const int b = blockIdx.x;
    const int t = threadIdx.x;
    if (b < QBLOCKS) {
        // ---- quant: matches jnp.round(jnp.clip(x / s, -128, 127)) ----
        const float s = __ldg(iscale);
        size_t i = (size_t)b * 256 + t;            // one per 8 elems
        const float4* xp = (const float4*)x;
        float4 a = xp[2 * i];
        float4 bb = xp[2 * i + 1];
        float v[8] = {a.x, a.y, a.z, a.w, bb.x, bb.y, bb.z, bb.w};
        uint32_t pk[4];
#pragma unroll
        for (int j = 0; j < 4; j++) {
            float q0 = rintf(fminf(fmaxf(__fdiv_rn(v[2 * j + 0], s), -128.0f), 127.0f));
            float q1 = rintf(fminf(fmaxf(__fdiv_rn(v[2 * j + 1], s), -128.0f), 127.0f));
            __half2 h = __floats2half2_rn(q0, q1);
            pk[j] = *reinterpret_cast<uint32_t*>(&h);
        }
        ((uint4*)g_Ah)[i] = make_uint4(pk[0], pk[1], pk[2], pk[3]);
    } else {
        // ---- transpose + narrow: W[K,N] int32 -> Wt[N,K] fp16 ----
        const int tb = b - QBLOCKS;
        const int n0 = (tb % TBX) * 64;
        const int k0 = (tb / TBX) * 64;
#pragma unroll
        for (int c = 0; c < 4; c++) {
            int idx = t + 256 * c;          // 0..1023 chunks of 4 int32
            int kk = idx >> 4;              // k row within tile (0..63)
            int nw = (idx & 15) * 4;        // n offset within tile
            int4 v = *(const int4*)(w + (size_t)(k0 + kk) * N_DIM + n0 + nw);
            tile[nw + 0][kk] = __int2half_rn(v.x);
            tile[nw + 1][kk] = __int2half_rn(v.y);
            tile[nw + 2][kk] = __int2half_rn(v.z);
            tile[nw + 3][kk] = __int2half_rn(v.w);
        }
        __syncthreads();
#pragma unroll
        for (int c = 0; c < 2; c++) {
            int idx = t + 256 * c;          // 64 rows x 8 chunks of 8 halves
            int nn = idx >> 3;
            int kc = (idx & 7) * 8;
            uint4 v = *(uint4*)&tile[nn][kc];
            *(uint4*)(g_Bth + (size_t)(n0 + nn) * K_DIM + k0 + kc) = v;
        }
    }
}

// ---------------- GEMM: fp16 HMMA + fused dequant ----------------
__global__ __launch_bounds__(NTHREADS, 2)
void gemm_kernel(const float* __restrict__ wscale, const float* __restrict__ iscale,
                 float* __restrict__ out) {
    extern __shared__ char smem[];
    const uint32_t sb = smem_u32(smem);
    const int tid = threadIdx.x;
    const int wid = tid >> 5;
    const int lane = tid & 31;
    const int warp_m = wid & 1;         // 2 warp rows (64 m each)
    const int warp_n = wid >> 1;        // 4 warp cols (32 n each)

    // rasterization: GROUP m-tiles sweep N together for L2 reuse of the A band
    const int NT = N_DIM / BN;          // 86
    const int GROUP = 16;
    int pid = blockIdx.x;
    int width = GROUP * NT;
    int group = pid / width;
    int rem = pid - group * width;
    int mt_idx = group * GROUP + (rem % GROUP);
    int nt_idx = rem / GROUP;
    const int m0 = mt_idx * BM;
    const int n0 = nt_idx * BN;

    // --------- precomputed cp.async addressing (kt-invariant parts) ---------
    const int ld_row = tid >> 3;         // 0..31
    const int ld_c   = tid & 7;          // 16B chunk
    const uint32_t ld_sw = (uint32_t)((ld_c ^ (ld_row & 7)) << 4);
    const uint32_t dst0 = (uint32_t)ld_row * ROW_BYTES + ld_sw;
    const char* a_src0 = ((const char*)g_Ah)  + ((size_t)(m0 + ld_row) * K_DIM) * 2 + ld_c * 16;
    const char* b_src0 = ((const char*)g_Bth) + ((size_t)(n0 + ld_row) * K_DIM) * 2 + ld_c * 16;
    const size_t row_step = (size_t)32 * K_DIM * 2;   // +32 rows

#define ISSUE_TILE(s, kt)                                                          \
    do {                                                                           \
        const uint32_t a_sti = sb + (s) * STAGE_BYTES;                             \
        const uint32_t b_sti = a_sti + A_STAGE_BYTES;                              \
        const char* a_p = a_src0 + (size_t)(kt) * ROW_BYTES;                       \
        const char* b_p = b_src0 + (size_t)(kt) * ROW_BYTES;                       \
        _Pragma("unroll")                                                          \
        for (int i = 0; i < 4; i++) {                                              \
            cp_async16(a_sti + dst0 + i * (32 * ROW_BYTES), a_p + i * row_step);   \
            cp_async16(b_sti + dst0 + i * (32 * ROW_BYTES), b_p + i * row_step);   \
        }                                                                          \
    } while (0)

    float acc[4][4][4];
#pragma unroll
    for (int i = 0; i < 4; i++)
#pragma unroll
        for (int j = 0; j < 4; j++)
#pragma unroll
            for (int k = 0; k < 4; k++) acc[i][j][k] = 0.0f;

    // prologue: stages 0,1 in flight
    ISSUE_TILE(0, 0); CP_COMMIT();
    ISSUE_TILE(1, 1); CP_COMMIT();

    // ldmatrix per-lane addressing (PTX m16n8k16 fragment tables)
    const int lw = lane & 7;
    const uint32_t a_row_off = (uint32_t)(warp_m * 64 + (lane & 15)) * ROW_BYTES;
    const uint32_t b_row_off = (uint32_t)(warp_n * 32 + ((lane >> 4) << 3) + (lane & 7)) * ROW_BYTES;
    const int a_hi = lane >> 4;          // 0..1
    const int b_hi = (lane >> 3) & 1;    // 0..1
    uint32_t a_ck[4], b_ck[4];
#pragma unroll
    for (int ks = 0; ks < 4; ks++) {
        a_ck[ks] = (uint32_t)(((2 * ks + a_hi) ^ lw) << 4);
        b_ck[ks] = (uint32_t)(((2 * ks + b_hi) ^ lw) << 4);
    }

#pragma unroll 3
    for (int kt = 0; kt < KTILES; kt++) {
        CP_WAIT(1);
        __syncthreads();

        const int s = kt % STAGES;
        const uint32_t a_st = sb + s * STAGE_BYTES;
        const uint32_t b_st = a_st + A_STAGE_BYTES;

        // software-pipelined fragment loads; cp.async burst issued after the
        // ks=0 mma block so the tensor pipe refills immediately post-barrier.
        uint32_t af[2][4][4], bf[2][2][4];
#pragma unroll
        for (int mt = 0; mt < 4; mt++)
            LDMX4(af[0][mt], a_st + a_row_off + (uint32_t)(mt * 16) * ROW_BYTES + a_ck[0]);
#pragma unroll
        for (int nq = 0; nq < 2; nq++)
            LDMX4(bf[0][nq], b_st + b_row_off + (uint32_t)(nq * 16) * ROW_BYTES + b_ck[0]);

#pragma unroll
        for (int ks = 0; ks < 4; ks++) {   // four k16 slices per BK=64
            const int cur = ks & 1, nxt = cur ^ 1;
            if (ks < 3) {
#pragma unroll
                for (int mt = 0; mt < 4; mt++)
                    LDMX4(af[nxt][mt], a_st + a_row_off + (uint32_t)(mt * 16) * ROW_BYTES + a_ck[ks + 1]);
#pragma unroll
                for (int nq = 0; nq < 2; nq++)
                    LDMX4(bf[nxt][nq], b_st + b_row_off + (uint32_t)(nq * 16) * ROW_BYTES + b_ck[ks + 1]);
            }
#pragma unroll
            for (int mt = 0; mt < 4; mt++)
#pragma unroll
                for (int nt = 0; nt < 4; nt++)
                    MMA_F16(acc[mt][nt], af[cur][mt],
                            bf[cur][nt >> 1][(nt & 1) * 2], bf[cur][nt >> 1][(nt & 1) * 2 + 1]);
            if (ks == 0) {
                // Overwrites stage (kt+2)%3 == (kt-1)%3: all warps finished
                // computing kt-1 before this kt's barrier, so it is safe.
                if (kt + 2 < KTILES) ISSUE_TILE((kt + 2) % STAGES, kt + 2);
                CP_COMMIT();   // unconditional: empty commit groups are legal
            }
        }
    }

    // ---- epilogue: fused dequant, fp32 stores ----
    const float sin = __ldg(iscale);
    const int m_base_g = m0 + warp_m * 64;
    const int n_base_g = n0 + warp_n * 32;
#pragma unroll
    for (int nt = 0; nt < 4; nt++) {
        const int n = n_base_g + nt * 8 + 2 * (lane & 3);
        const float w0 = sin * __ldg(wscale + n);
        const float w1 = sin * __ldg(wscale + n + 1);
#pragma unroll
        for (int mt = 0; mt < 4; mt++) {
            const int r0 = m_base_g + mt * 16 + (lane >> 2);
            float2 v0, v1;
            v0.x = acc[mt][nt][0] * w0;
            v0.y = acc[mt][nt][1] * w1;
            v1.x = acc[mt][nt][2] * w0;
            v1.y = acc[mt][nt][3] * w1;
            *(float2*)(out + (size_t)r0 * N_DIM + n) = v0;
            *(float2*)(out + (size_t)(r0 + 8) * N_DIM + n) = v1;
        }
    }
#undef ISSUE_TILE
}

// ---------------- launch ----------------
extern "C" void kernel_launch(void* const* d_in, const int* in_sizes, int n_in,
                              void* d_out, int out_size) {
    (void)out_size;
    // Inputs identified by element count; qweight arrives as int32.
    const float* x  = nullptr;
    const int*   w  = nullptr;
    const float* ws = nullptr;
    const float* is = nullptr;
    const long long XE = (long long)M_DIM * K_DIM;
    const long long WE = (long long)K_DIM * N_DIM;
    for (int i = 0; i < n_in; i++) {
        long long sz = in_sizes[i];
        if (sz == XE)           x  = (const float*)d_in[i];
        else if (sz == WE)      w  = (const int*)d_in[i];
        else if (sz == N_DIM)   ws = (const float*)d_in[i];
        else if (sz == 1)       is = (const float*)d_in[i];
    }
    if (!x)  x  = (const float*)d_in[0];
    if (!w)  w  = (const int*)d_in[1];
    if (!ws) ws = (const float*)d_in[2];
    if (!is) is = (const float*)d_in[3];
    float* out = (float*)d_out;

    // 1) fused pre-pass: quant (x) + transpose/narrow (W), run concurrently
    prep_kernel<<<QBLOCKS + TBLOCKS, 256>>>(x, w, is);

    // 2) fp16 tensor-core GEMM + fused dequant (2 CTAs/SM)
    cudaFuncSetAttribute(gemm_kernel, cudaFuncAttributeMaxDynamicSharedMemorySize, SMEM_BYTES);
    gemm_kernel<<<(M_DIM / BM) * (N_DIM / BN), NTHREADS, SMEM_BYTES>>>(ws, is, out);
}

// round 14
// speedup vs baseline: 1.0896x; 1.0896x over previous
#include <cuda_runtime.h>
#include <cuda_fp16.h>
#include <cstdint>

// Problem dims (fixed by the dataset)
#define M_DIM 8192
#define K_DIM 4096
#define N_DIM 11008

// GEMM tiling
#define BM 128
#define BN 128
#define BK 64                 // fp16 elems per k-tile = 128 bytes per row
#define STAGES 3
#define KTILES (K_DIM / BK)   // 64
#define NTHREADS 256

#define ROW_BYTES 128                      // 64 halves; XOR-swizzled chunks, no pad
#define A_STAGE_BYTES (BM * ROW_BYTES)     // 16384
#define B_STAGE_BYTES (BN * ROW_BYTES)     // 16384
#define STAGE_BYTES (A_STAGE_BYTES + B_STAGE_BYTES)
#define SMEM_BYTES (STAGES * STAGE_BYTES)  // 98304 -> 2 CTAs/SM

// Scratch (device globals: allocation-free rule)
__device__ __align__(128) __half g_Ah [(size_t)M_DIM * K_DIM];  // 64 MB quantized x as fp16 ints
__device__ __align__(128) __half g_Bth[(size_t)N_DIM * K_DIM];  // 90 MB W^T [N,K] fp16

// ---------------- PTX helpers (baseline ISA only) ----------------
__device__ __forceinline__ uint32_t smem_u32(const void* p) {
    uint32_t a;
    asm("{ .reg .u64 t; cvta.to.shared.u64 t, %1; cvt.u32.u64 %0, t; }" : "=r"(a) : "l"(p));
    return a;
}
__device__ __forceinline__ void cp_async16(uint32_t dst, const void* src) {
    asm volatile("cp.async.cg.shared.global [%0], [%1], 16;" :: "r"(dst), "l"(src));
}
#define CP_COMMIT() asm volatile("cp.async.commit_group;" ::: "memory")
#define CP_WAIT(n)  asm volatile("cp.async.wait_group %0;" :: "n"(n) : "memory")

#define LDMX4(r, addr) \
    asm volatile("ldmatrix.sync.aligned.m8n8.x4.shared.b16 {%0,%1,%2,%3}, [%4];" \
        : "=r"((r)[0]), "=r"((r)[1]), "=r"((r)[2]), "=r"((r)[3]) : "r"(addr))

// m16n8k16 fp16 inputs, fp32 accumulate — C=D in place.
#define MMA_F16(d, a, b0, b1) \
    asm volatile("mma.sync.aligned.m16n8k16.row.col.f32.f16.f16.f32 " \
        "{%0,%1,%2,%3}, {%4,%5,%6,%7}, {%8,%9}, {%0,%1,%2,%3};" \
        : "+f"((d)[0]), "+f"((d)[1]), "+f"((d)[2]), "+f"((d)[3]) \
        : "r"((a)[0]), "r"((a)[1]), "r"((a)[2]), "r"((a)[3]), "r"(b0), "r"(b1))

// -------- Fused pre-pass: quant (x -> fp16 ints) + transpose (W int32 -> Wt fp16) ----
// Blocks [0, QBLOCKS) quantize; blocks [QBLOCKS, QBLOCKS+TBLOCKS) transpose.
// The two tasks are independent; fusing them into one launch lets them run
// concurrently instead of serializing on the stream.
#define QBLOCKS ((M_DIM * K_DIM / 8) / 256)                 // 16384
#define TBX (N_DIM / 64)                                    // 172
#define TBLOCKS (TBX * (K_DIM / 64))                        // 11008

__global__ __launch_bounds__(256, 8)
void prep_kernel(const float* __restrict__ x, const int* __restrict__ w,
                 const float* __restrict__ iscale) {
    __shared__ __align__(16) __half tile[64][72];  // transpose staging (unused by quant blocks)
    const int b = blockIdx.x;
    const int t = threadIdx.x;
    if (b < QBLOCKS) {
        // ---- quant: matches jnp.round(jnp.clip(x / s, -128, 127)) ----
        const float s = __ldg(iscale);
        size_t i = (size_t)b * 256 + t;            // one per 8 elems
        const float4* xp = (const float4*)x;
        float4 a = xp[2 * i];
        float4 bb = xp[2 * i + 1];
        float v[8] = {a.x, a.y, a.z, a.w, bb.x, bb.y, bb.z, bb.w};
        uint32_t pk[4];
#pragma unroll
        for (int j = 0; j < 4; j++) {
            float q0 = rintf(fminf(fmaxf(__fdiv_rn(v[2 * j + 0], s), -128.0f), 127.0f));
            float q1 = rintf(fminf(fmaxf(__fdiv_rn(v[2 * j + 1], s), -128.0f), 127.0f));
            __half2 h = __floats2half2_rn(q0, q1);
            pk[j] = *reinterpret_cast<uint32_t*>(&h);
        }
        ((uint4*)g_Ah)[i] = make_uint4(pk[0], pk[1], pk[2], pk[3]);
    } else {
        // ---- transpose + narrow: W[K,N] int32 -> Wt[N,K] fp16 ----
        const int tb = b - QBLOCKS;
        const int n0 = (tb % TBX) * 64;
        const int k0 = (tb / TBX) * 64;
#pragma unroll
        for (int c = 0; c < 4; c++) {
            int idx = t + 256 * c;          // 0..1023 chunks of 4 int32
            int kk = idx >> 4;              // k row within tile (0..63)
            int nw = (idx & 15) * 4;        // n offset within tile
            int4 v = *(const int4*)(w + (size_t)(k0 + kk) * N_DIM + n0 + nw);
            tile[nw + 0][kk] = __int2half_rn(v.x);
            tile[nw + 1][kk] = __int2half_rn(v.y);
            tile[nw + 2][kk] = __int2half_rn(v.z);
            tile[nw + 3][kk] = __int2half_rn(v.w);
        }
        __syncthreads();
#pragma unroll
        for (int c = 0; c < 2; c++) {
            int idx = t + 256 * c;          // 64 rows x 8 chunks of 8 halves
            int nn = idx >> 3;
            int kc = (idx & 7) * 8;
            uint4 v = *(uint4*)&tile[nn][kc];
            *(uint4*)(g_Bth + (size_t)(n0 + nn) * K_DIM + k0 + kc) = v;
        }
    }
}

// ---------------- GEMM: fp16 HMMA + fused dequant ----------------
__global__ __launch_bounds__(NTHREADS, 2)
void gemm_kernel(const float* __restrict__ wscale, const float* __restrict__ iscale,
                 float* __restrict__ out) {
    extern __shared__ char smem[];
    const uint32_t sb = smem_u32(smem);
    const int tid = threadIdx.x;
    const int wid = tid >> 5;
    const int lane = tid & 31;
    const int warp_m = wid & 1;         // 2 warp rows (64 m each)
    const int warp_n = wid >> 1;        // 4 warp cols (32 n each)

    // rasterization: GROUP m-tiles sweep N together for L2 reuse of the A band
    const int NT = N_DIM / BN;          // 86
    const int GROUP = 16;
    int pid = blockIdx.x;
    int width = GROUP * NT;
    int group = pid / width;
    int rem = pid - group * width;
    int mt_idx = group * GROUP + (rem % GROUP);
    int nt_idx = rem / GROUP;
    const int m0 = mt_idx * BM;
    const int n0 = nt_idx * BN;

    // --------- precomputed cp.async addressing (kt-invariant parts) ---------
    const int ld_row = tid >> 3;         // 0..31
    const int ld_c   = tid & 7;          // 16B chunk
    const uint32_t ld_sw = (uint32_t)((ld_c ^ (ld_row & 7)) << 4);
    const uint32_t dst0 = (uint32_t)ld_row * ROW_BYTES + ld_sw;
    const char* a_src0 = ((const char*)g_Ah)  + ((size_t)(m0 + ld_row) * K_DIM) * 2 + ld_c * 16;
    const char* b_src0 = ((const char*)g_Bth) + ((size_t)(n0 + ld_row) * K_DIM) * 2 + ld_c * 16;
    const size_t row_step = (size_t)32 * K_DIM * 2;   // +32 rows

#define ISSUE_TILE(s, kt)                                                          \
    do {                                                                           \
        const uint32_t a_sti = sb + (s) * STAGE_BYTES;                             \
        const uint32_t b_sti = a_sti + A_STAGE_BYTES;                              \
        const char* a_p = a_src0 + (size_t)(kt) * ROW_BYTES;                       \
        const char* b_p = b_src0 + (size_t)(kt) * ROW_BYTES;                       \
        _Pragma("unroll")                                                          \
        for (int i = 0; i < 4; i++) {                                              \
            cp_async16(a_sti + dst0 + i * (32 * ROW_BYTES), a_p + i * row_step);   \
            cp_async16(b_sti + dst0 + i * (32 * ROW_BYTES), b_p + i * row_step);   \
        }                                                                          \
    } while (0)

    float acc[4][4][4];
#pragma unroll
    for (int i = 0; i < 4; i++)
#pragma unroll
        for (int j = 0; j < 4; j++)
#pragma unroll
            for (int k = 0; k < 4; k++) acc[i][j][k] = 0.0f;

    // prologue: stages 0,1 in flight
    ISSUE_TILE(0, 0); CP_COMMIT();
    ISSUE_TILE(1, 1); CP_COMMIT();

    // ldmatrix per-lane addressing (PTX m16n8k16 fragment tables)
    const int lw = lane & 7;
    const uint32_t a_row_off = (uint32_t)(warp_m * 64 + (lane & 15)) * ROW_BYTES;
    const uint32_t b_row_off = (uint32_t)(warp_n * 32 + ((lane >> 4) << 3) + (lane & 7)) * ROW_BYTES;
    const int a_hi = lane >> 4;          // 0..1
    const int b_hi = (lane >> 3) & 1;    // 0..1
    uint32_t a_ck[4], b_ck[4];
#pragma unroll
    for (int ks = 0; ks < 4; ks++) {
        a_ck[ks] = (uint32_t)(((2 * ks + a_hi) ^ lw) << 4);
        b_ck[ks] = (uint32_t)(((2 * ks + b_hi) ^ lw) << 4);
    }

#pragma unroll 6
    for (int kt = 0; kt < KTILES; kt++) {
        CP_WAIT(1);
        __syncthreads();

        const int s = kt % STAGES;
        const uint32_t a_st = sb + s * STAGE_BYTES;
        const uint32_t b_st = a_st + A_STAGE_BYTES;

        // software-pipelined fragment loads; cp.async burst issued after the
        // ks=0 mma block so the tensor pipe refills immediately post-barrier.
        uint32_t af[2][4][4], bf[2][2][4];
#pragma unroll
        for (int mt = 0; mt < 4; mt++)
            LDMX4(af[0][mt], a_st + a_row_off + (uint32_t)(mt * 16) * ROW_BYTES + a_ck[0]);
#pragma unroll
        for (int nq = 0; nq < 2; nq++)
            LDMX4(bf[0][nq], b_st + b_row_off + (uint32_t)(nq * 16) * ROW_BYTES + b_ck[0]);

        bool issued = false;
#pragma unroll
        for (int ks = 0; ks < 4; ks++) {   // four k16 slices per BK=64
            const int cur = ks & 1, nxt = cur ^ 1;
            if (ks < 3) {
#pragma unroll
                for (int mt = 0; mt < 4; mt++)
                    LDMX4(af[nxt][mt], a_st + a_row_off + (uint32_t)(mt * 16) * ROW_BYTES + a_ck[ks + 1]);
#pragma unroll
                for (int nq = 0; nq < 2; nq++)
                    LDMX4(bf[nxt][nq], b_st + b_row_off + (uint32_t)(nq * 16) * ROW_BYTES + b_ck[ks + 1]);
            }
#pragma unroll
            for (int mt = 0; mt < 4; mt++)
#pragma unroll
                for (int nt = 0; nt < 4; nt++)
                    MMA_F16(acc[mt][nt], af[cur][mt],
                            bf[cur][nt >> 1][(nt & 1) * 2], bf[cur][nt >> 1][(nt & 1) * 2 + 1]);
            if (ks == 0 && kt + 2 < KTILES) {
                // Overwrites stage (kt+2)%3 == (kt-1)%3: all warps finished
                // computing kt-1 before this kt's barrier, so it is safe.
                ISSUE_TILE((kt + 2) % STAGES, kt + 2);
                issued = true;
            }
        }
        if (issued || kt + 2 >= KTILES) CP_COMMIT();
    }

    // ---- epilogue: fused dequant, fp32 stores ----
    const float sin = __ldg(iscale);
    const int m_base_g = m0 + warp_m * 64;
    const int n_base_g = n0 + warp_n * 32;
#pragma unroll
    for (int nt = 0; nt < 4; nt++) {
        const int n = n_base_g + nt * 8 + 2 * (lane & 3);
        const float w0 = sin * __ldg(wscale + n);
        const float w1 = sin * __ldg(wscale + n + 1);
#pragma unroll
        for (int mt = 0; mt < 4; mt++) {
            const int r0 = m_base_g + mt * 16 + (lane >> 2);
            float2 v0, v1;
            v0.x = acc[mt][nt][0] * w0;
            v0.y = acc[mt][nt][1] * w1;
            v1.x = acc[mt][nt][2] * w0;
            v1.y = acc[mt][nt][3] * w1;
            *(float2*)(out + (size_t)r0 * N_DIM + n) = v0;
            *(float2*)(out + (size_t)(r0 + 8) * N_DIM + n) = v1;
        }
    }
#undef ISSUE_TILE
}

// ---------------- launch ----------------
extern "C" void kernel_launch(void* const* d_in, const int* in_sizes, int n_in,
                              void* d_out, int out_size) {
    (void)out_size;
    // Inputs identified by element count; qweight arrives as int32.
    const float* x  = nullptr;
    const int*   w  = nullptr;
    const float* ws = nullptr;
    const float* is = nullptr;
    const long long XE = (long long)M_DIM * K_DIM;
    const long long WE = (long long)K_DIM * N_DIM;
    for (int i = 0; i < n_in; i++) {
        long long sz = in_sizes[i];
        if (sz == XE)           x  = (const float*)d_in[i];
        else if (sz == WE)      w  = (const int*)d_in[i];
        else if (sz == N_DIM)   ws = (const float*)d_in[i];
        else if (sz == 1)       is = (const float*)d_in[i];
    }
    if (!x)  x  = (const float*)d_in[0];
    if (!w)  w  = (const int*)d_in[1];
    if (!ws) ws = (const float*)d_in[2];
    if (!is) is = (const float*)d_in[3];
    float* out = (float*)d_out;

    // 1) fused pre-pass: quant (x) + transpose/narrow (W), run concurrently
    prep_kernel<<<QBLOCKS + TBLOCKS, 256>>>(x, w, is);

    // 2) fp16 tensor-core GEMM + fused dequant (2 CTAs/SM)
    cudaFuncSetAttribute(gemm_kernel, cudaFuncAttributeMaxDynamicSharedMemorySize, SMEM_BYTES);
    gemm_kernel<<<(M_DIM / BM) * (N_DIM / BN), NTHREADS, SMEM_BYTES>>>(ws, is, out);
}

// round 15
// speedup vs baseline: 1.0898x; 1.0001x over previous
#include <cuda_runtime.h>
#include <cuda_fp16.h>
#include <cstdint>

// Problem dims (fixed by the dataset)
#define M_DIM 8192
#define K_DIM 4096
#define N_DIM 11008

// GEMM tiling
#define BM 128
#define BN 128
#define BK 64                 // fp16 elems per k-tile = 128 bytes per row
#define STAGES 3
#define KTILES (K_DIM / BK)   // 64
#define NTHREADS 256

#define ROW_BYTES 128                      // 64 halves; XOR-swizzled chunks, no pad
#define A_STAGE_BYTES (BM * ROW_BYTES)     // 16384
#define B_STAGE_BYTES (BN * ROW_BYTES)     // 16384
#define STAGE_BYTES (A_STAGE_BYTES + B_STAGE_BYTES)
#define SMEM_BYTES (STAGES * STAGE_BYTES)  // 98304 -> 2 CTAs/SM

// Scratch (device globals: allocation-free rule)
__device__ __align__(128) __half g_Ah [(size_t)M_DIM * K_DIM];  // 64 MB quantized x as fp16 ints
__device__ __align__(128) __half g_Bth[(size_t)N_DIM * K_DIM];  // 90 MB W^T [N,K] fp16

// ---------------- PTX helpers (baseline ISA only) ----------------
__device__ __forceinline__ uint32_t smem_u32(const void* p) {
    uint32_t a;
    asm("{ .reg .u64 t; cvta.to.shared.u64 t, %1; cvt.u32.u64 %0, t; }" : "=r"(a) : "l"(p));
    return a;
}
__device__ __forceinline__ void cp_async16(uint32_t dst, const void* src) {
    asm volatile("cp.async.cg.shared.global [%0], [%1], 16;" :: "r"(dst), "l"(src));
}
#define CP_COMMIT() asm volatile("cp.async.commit_group;" ::: "memory")
#define CP_WAIT(n)  asm volatile("cp.async.wait_group %0;" :: "n"(n) : "memory")

#define LDMX4(r, addr) \
    asm volatile("ldmatrix.sync.aligned.m8n8.x4.shared.b16 {%0,%1,%2,%3}, [%4];" \
        : "=r"((r)[0]), "=r"((r)[1]), "=r"((r)[2]), "=r"((r)[3]) : "r"(addr))

// m16n8k16 fp16 inputs, fp32 accumulate — C=D in place.
#define MMA_F16(d, a, b0, b1) \
    asm volatile("mma.sync.aligned.m16n8k16.row.col.f32.f16.f16.f32 " \
        "{%0,%1,%2,%3}, {%4,%5,%6,%7}, {%8,%9}, {%0,%1,%2,%3};" \
        : "+f"((d)[0]), "+f"((d)[1]), "+f"((d)[2]), "+f"((d)[3]) \
        : "r"((a)[0]), "r"((a)[1]), "r"((a)[2]), "r"((a)[3]), "r"(b0), "r"(b1))

// -------- Fused pre-pass: quant (x -> fp16 ints) + transpose (W int32 -> Wt fp16) ----
// Blocks [0, QBLOCKS) quantize; blocks [QBLOCKS, QBLOCKS+TBLOCKS) transpose.
#define QBLOCKS ((M_DIM * K_DIM / 8) / 256)                 // 16384
#define TBX (N_DIM / 64)                                    // 172
#define TBLOCKS (TBX * (K_DIM / 64))                        // 11008

__global__ __launch_bounds__(256, 8)
void prep_kernel(const float* __restrict__ x, const int* __restrict__ w,
                 const float* __restrict__ iscale) {
    __shared__ __align__(16) __half tile[64][72];  // transpose staging (unused by quant blocks)
    const int b = blockIdx.x;
    const int t = threadIdx.x;
    if (b < QBLOCKS) {
        // ---- quant: matches jnp.round(jnp.clip(x / s, -128, 127)) ----
        const float s = __ldg(iscale);
        size_t i = (size_t)b * 256 + t;            // one per 8 elems
        const float4* xp = (const float4*)x;
        float4 a = xp[2 * i];
        float4 bb = xp[2 * i + 1];
        float v[8] = {a.x, a.y, a.z, a.w, bb.x, bb.y, bb.z, bb.w};
        uint32_t pk[4];
#pragma unroll
        for (int j = 0; j < 4; j++) {
            float q0 = rintf(fminf(fmaxf(__fdiv_rn(v[2 * j + 0], s), -128.0f), 127.0f));
            float q1 = rintf(fminf(fmaxf(__fdiv_rn(v[2 * j + 1], s), -128.0f), 127.0f));
            __half2 h = __floats2half2_rn(q0, q1);
            pk[j] = *reinterpret_cast<uint32_t*>(&h);
        }
        ((uint4*)g_Ah)[i] = make_uint4(pk[0], pk[1], pk[2], pk[3]);
    } else {
        // ---- transpose + narrow: W[K,N] int32 -> Wt[N,K] fp16 ----
        const int tb = b - QBLOCKS;
        const int n0 = (tb % TBX) * 64;
        const int k0 = (tb / TBX) * 64;
#pragma unroll
        for (int c = 0; c < 4; c++) {
            int idx = t + 256 * c;          // 0..1023 chunks of 4 int32
            int kk = idx >> 4;              // k row within tile (0..63)
            int nw = (idx & 15) * 4;        // n offset within tile
            int4 v = *(const int4*)(w + (size_t)(k0 + kk) * N_DIM + n0 + nw);
            tile[nw + 0][kk] = __int2half_rn(v.x);
            tile[nw + 1][kk] = __int2half_rn(v.y);
            tile[nw + 2][kk] = __int2half_rn(v.z);
            tile[nw + 3][kk] = __int2half_rn(v.w);
        }
        __syncthreads();
#pragma unroll
        for (int c = 0; c < 2; c++) {
            int idx = t + 256 * c;          // 64 rows x 8 chunks of 8 halves
            int nn = idx >> 3;
            int kc = (idx & 7) * 8;
            uint4 v = *(uint4*)&tile[nn][kc];
            *(uint4*)(g_Bth + (size_t)(n0 + nn) * K_DIM + k0 + kc) = v;
        }
    }
}

// ---------------- GEMM: fp16 HMMA + fused dequant ----------------
__global__ __launch_bounds__(NTHREADS, 2)
void gemm_kernel(const float* __restrict__ wscale, const float* __restrict__ iscale,
                 float* __restrict__ out) {
    extern __shared__ char smem[];
    const uint32_t sb = smem_u32(smem);
    const int tid = threadIdx.x;
    const int wid = tid >> 5;
    const int lane = tid & 31;
    const int warp_m = wid & 1;         // 2 warp rows (64 m each)
    const int warp_n = wid >> 1;        // 4 warp cols (32 n each)

    // rasterization: GROUP m-tiles sweep N together for L2 reuse of the A band
    const int NT = N_DIM / BN;          // 86
    const int GROUP = 16;
    int pid = blockIdx.x;
    int width = GROUP * NT;
    int group = pid / width;
    int rem = pid - group * width;
    int mt_idx = group * GROUP + (rem % GROUP);
    int nt_idx = rem / GROUP;
    const int m0 = mt_idx * BM;
    const int n0 = nt_idx * BN;

    // --------- precomputed cp.async addressing (kt-invariant parts) ---------
    const int ld_row = tid >> 3;         // 0..31
    const int ld_c   = tid & 7;          // 16B chunk
    const uint32_t ld_sw = (uint32_t)((ld_c ^ (ld_row & 7)) << 4);
    const uint32_t dst0 = (uint32_t)ld_row * ROW_BYTES + ld_sw;
    const char* a_src0 = ((const char*)g_Ah)  + ((size_t)(m0 + ld_row) * K_DIM) * 2 + ld_c * 16;
    const char* b_src0 = ((const char*)g_Bth) + ((size_t)(n0 + ld_row) * K_DIM) * 2 + ld_c * 16;
    const size_t row_step = (size_t)32 * K_DIM * 2;   // +32 rows

#define ISSUE_TILE(s, kt)                                                          \
    do {                                                                           \
        const uint32_t a_sti = sb + (s) * STAGE_BYTES;                             \
        const uint32_t b_sti = a_sti + A_STAGE_BYTES;                              \
        const char* a_p = a_src0 + (size_t)(kt) * ROW_BYTES;                       \
        const char* b_p = b_src0 + (size_t)(kt) * ROW_BYTES;                       \
        _Pragma("unroll")                                                          \
        for (int i = 0; i < 4; i++) {                                              \
            cp_async16(a_sti + dst0 + i * (32 * ROW_BYTES), a_p + i * row_step);   \
            cp_async16(b_sti + dst0 + i * (32 * ROW_BYTES), b_p + i * row_step);   \
        }                                                                          \
    } while (0)

    float acc[4][4][4];
#pragma unroll
    for (int i = 0; i < 4; i++)
#pragma unroll
        for (int j = 0; j < 4; j++)
#pragma unroll
            for (int k = 0; k < 4; k++) acc[i][j][k] = 0.0f;

    // prologue: stages 0,1 in flight
    ISSUE_TILE(0, 0); CP_COMMIT();
    ISSUE_TILE(1, 1); CP_COMMIT();

    // ldmatrix per-lane addressing (PTX m16n8k16 fragment tables)
    const int lw = lane & 7;
    const uint32_t a_row_off = (uint32_t)(warp_m * 64 + (lane & 15)) * ROW_BYTES;
    const uint32_t b_row_off = (uint32_t)(warp_n * 32 + ((lane >> 4) << 3) + (lane & 7)) * ROW_BYTES;
    const int a_hi = lane >> 4;          // 0..1
    const int b_hi = (lane >> 3) & 1;    // 0..1
    uint32_t a_ck[4], b_ck[4];
#pragma unroll
    for (int ks = 0; ks < 4; ks++) {
        a_ck[ks] = (uint32_t)(((2 * ks + a_hi) ^ lw) << 4);
        b_ck[ks] = (uint32_t)(((2 * ks + b_hi) ^ lw) << 4);
    }

#pragma unroll 6
    for (int kt = 0; kt < KTILES; kt++) {
        CP_WAIT(1);
        __syncthreads();

        const int s = kt % STAGES;
        const uint32_t a_st = sb + s * STAGE_BYTES;
        const uint32_t b_st = a_st + A_STAGE_BYTES;

        // software-pipelined fragment loads; cp.async burst issued after the
        // ks=0 mma block so the tensor pipe refills immediately post-barrier.
        uint32_t af[2][4][4], bf[2][2][4];
#pragma unroll
        for (int mt = 0; mt < 4; mt++)
            LDMX4(af[0][mt], a_st + a_row_off + (uint32_t)(mt * 16) * ROW_BYTES + a_ck[0]);
#pragma unroll
        for (int nq = 0; nq < 2; nq++)
            LDMX4(bf[0][nq], b_st + b_row_off + (uint32_t)(nq * 16) * ROW_BYTES + b_ck[0]);

#pragma unroll
        for (int ks = 0; ks < 4; ks++) {   // four k16 slices per BK=64
            const int cur = ks & 1, nxt = cur ^ 1;
            if (ks < 3) {
#pragma unroll
                for (int mt = 0; mt < 4; mt++)
                    LDMX4(af[nxt][mt], a_st + a_row_off + (uint32_t)(mt * 16) * ROW_BYTES + a_ck[ks + 1]);
#pragma unroll
                for (int nq = 0; nq < 2; nq++)
                    LDMX4(bf[nxt][nq], b_st + b_row_off + (uint32_t)(nq * 16) * ROW_BYTES + b_ck[ks + 1]);
            }
#pragma unroll
            for (int mt = 0; mt < 4; mt++)
#pragma unroll
                for (int nt = 0; nt < 4; nt++)
                    MMA_F16(acc[mt][nt], af[cur][mt],
                            bf[cur][nt >> 1][(nt & 1) * 2], bf[cur][nt >> 1][(nt & 1) * 2 + 1]);
            if (ks == 0) {
                // Overwrites stage (kt+2)%3 == (kt-1)%3: all warps finished
                // computing kt-1 before this kt's barrier, so it is safe.
                if (kt + 2 < KTILES) ISSUE_TILE((kt + 2) % STAGES, kt + 2);
                CP_COMMIT();   // unconditional: empty commit groups are legal
            }
        }
    }

    // ---- epilogue: fused dequant, fp32 stores ----
    const float sin = __ldg(iscale);
    const int m_base_g = m0 + warp_m * 64;
    const int n_base_g = n0 + warp_n * 32;
#pragma unroll
    for (int nt = 0; nt < 4; nt++) {
        const int n = n_base_g + nt * 8 + 2 * (lane & 3);
        const float w0 = sin * __ldg(wscale + n);
        const float w1 = sin * __ldg(wscale + n + 1);
#pragma unroll
        for (int mt = 0; mt < 4; mt++) {
            const int r0 = m_base_g + mt * 16 + (lane >> 2);
            float2 v0, v1;
            v0.x = acc[mt][nt][0] * w0;
            v0.y = acc[mt][nt][1] * w1;
            v1.x = acc[mt][nt][2] * w0;
            v1.y = acc[mt][nt][3] * w1;
            *(float2*)(out + (size_t)r0 * N_DIM + n) = v0;
            *(float2*)(out + (size_t)(r0 + 8) * N_DIM + n) = v1;
        }
    }
#undef ISSUE_TILE
}

// ---------------- launch ----------------
extern "C" void kernel_launch(void* const* d_in, const int* in_sizes, int n_in,
                              void* d_out, int out_size) {
    (void)out_size;
    // Inputs identified by element count; qweight arrives as int32.
    const float* x  = nullptr;
    const int*   w  = nullptr;
    const float* ws = nullptr;
    const float* is = nullptr;
    const long long XE = (long long)M_DIM * K_DIM;
    const long long WE = (long long)K_DIM * N_DIM;
    for (int i = 0; i < n_in; i++) {
        long long sz = in_sizes[i];
        if (sz == XE)           x  = (const float*)d_in[i];
        else if (sz == WE)      w  = (const int*)d_in[i];
        else if (sz == N_DIM)   ws = (const float*)d_in[i];
        else if (sz == 1)       is = (const float*)d_in[i];
    }
    if (!x)  x  = (const float*)d_in[0];
    if (!w)  w  = (const int*)d_in[1];
    if (!ws) ws = (const float*)d_in[2];
    if (!is) is = (const float*)d_in[3];
    float* out = (float*)d_out;

    // 1) fused pre-pass: quant (x) + transpose/narrow (W), run concurrently
    prep_kernel<<<QBLOCKS + TBLOCKS, 256>>>(x, w, is);

    // 2) fp16 tensor-core GEMM + fused dequant (2 CTAs/SM)
    cudaFuncSetAttribute(gemm_kernel, cudaFuncAttributeMaxDynamicSharedMemorySize, SMEM_BYTES);
    gemm_kernel<<<(M_DIM / BM) * (N_DIM / BN), NTHREADS, SMEM_BYTES>>>(ws, is, out);
}

// round 16
// speedup vs baseline: 1.1059x; 1.0148x over previous
#include <cuda_runtime.h>
#include <cuda_fp16.h>
#include <cstdint>

// Problem dims (fixed by the dataset)
#define M_DIM 8192
#define K_DIM 4096
#define N_DIM 11008

// GEMM tiling
#define BM 128
#define BN 128
#define BK 64                 // fp16 elems per k-tile = 128 bytes per row
#define STAGES 3
#define KTILES (K_DIM / BK)   // 64
#define NTHREADS 256

#define ROW_BYTES 128                      // 64 halves; XOR-swizzled chunks, no pad
#define A_STAGE_BYTES (BM * ROW_BYTES)     // 16384
#define B_STAGE_BYTES (BN * ROW_BYTES)     // 16384
#define STAGE_BYTES (A_STAGE_BYTES + B_STAGE_BYTES)
#define SMEM_BYTES (STAGES * STAGE_BYTES)  // 98304 -> 2 CTAs/SM

// Scratch (device globals: allocation-free rule)
__device__ __align__(128) __half g_Ah [(size_t)M_DIM * K_DIM];  // 64 MB quantized x as fp16 ints
__device__ __align__(128) __half g_Bth[(size_t)N_DIM * K_DIM];  // 90 MB W^T [N,K] fp16

// ---------------- PTX helpers (baseline ISA only) ----------------
__device__ __forceinline__ uint32_t smem_u32(const void* p) {
    uint32_t a;
    asm("{ .reg .u64 t; cvta.to.shared.u64 t, %1; cvt.u32.u64 %0, t; }" : "=r"(a) : "l"(p));
    return a;
}
__device__ __forceinline__ void cp_async16(uint32_t dst, const void* src) {
    asm volatile("cp.async.cg.shared.global [%0], [%1], 16;" :: "r"(dst), "l"(src));
}
#define CP_COMMIT() asm volatile("cp.async.commit_group;" ::: "memory")
#define CP_WAIT(n)  asm volatile("cp.async.wait_group %0;" :: "n"(n) : "memory")

#define LDMX4(r, addr) \
    asm volatile("ldmatrix.sync.aligned.m8n8.x4.shared.b16 {%0,%1,%2,%3}, [%4];" \
        : "=r"((r)[0]), "=r"((r)[1]), "=r"((r)[2]), "=r"((r)[3]) : "r"(addr))

// m16n8k16 fp16 inputs, fp32 accumulate — C=D in place.
#define MMA_F16(d, a, b0, b1) \
    asm volatile("mma.sync.aligned.m16n8k16.row.col.f32.f16.f16.f32 " \
        "{%0,%1,%2,%3}, {%4,%5,%6,%7}, {%8,%9}, {%0,%1,%2,%3};" \
        : "+f"((d)[0]), "+f"((d)[1]), "+f"((d)[2]), "+f"((d)[3]) \
        : "r"((a)[0]), "r"((a)[1]), "r"((a)[2]), "r"((a)[3]), "r"(b0), "r"(b1))

// -------- Fused pre-pass: quant (x -> fp16 ints) + transpose (W int32 -> Wt fp16) ----
// Blocks [0, QBLOCKS) quantize; blocks [QBLOCKS, QBLOCKS+TBLOCKS) transpose.
#define QBLOCKS ((M_DIM * K_DIM / 8) / 256)                 // 16384
#define TBX (N_DIM / 64)                                    // 172
#define TBLOCKS (TBX * (K_DIM / 64))                        // 11008

__global__ __launch_bounds__(256, 8)
void prep_kernel(const float* __restrict__ x, const int* __restrict__ w,
                 const float* __restrict__ iscale) {
    __shared__ __align__(16) __half tile[64][72];  // transpose staging (unused by quant blocks)
    const int b = blockIdx.x;
    const int t = threadIdx.x;
    if (b < QBLOCKS) {
        // ---- quant: matches jnp.round(jnp.clip(x / s, -128, 127)) ----
        const float s = __ldg(iscale);
        size_t i = (size_t)b * 256 + t;            // one per 8 elems
        const float4* xp = (const float4*)x;
        float4 a = xp[2 * i];
        float4 bb = xp[2 * i + 1];
        float v[8] = {a.x, a.y, a.z, a.w, bb.x, bb.y, bb.z, bb.w};
        uint32_t pk[4];
#pragma unroll
        for (int j = 0; j < 4; j++) {
            float q0 = rintf(fminf(fmaxf(__fdiv_rn(v[2 * j + 0], s), -128.0f), 127.0f));
            float q1 = rintf(fminf(fmaxf(__fdiv_rn(v[2 * j + 1], s), -128.0f), 127.0f));
            __half2 h = __floats2half2_rn(q0, q1);
            pk[j] = *reinterpret_cast<uint32_t*>(&h);
        }
        ((uint4*)g_Ah)[i] = make_uint4(pk[0], pk[1], pk[2], pk[3]);
    } else {
        // ---- transpose + narrow: W[K,N] int32 -> Wt[N,K] fp16 ----
        const int tb = b - QBLOCKS;
        const int n0 = (tb % TBX) * 64;
        const int k0 = (tb / TBX) * 64;
#pragma unroll
        for (int c = 0; c < 4; c++) {
            int idx = t + 256 * c;          // 0..1023 chunks of 4 int32
            int kk = idx >> 4;              // k row within tile (0..63)
            int nw = (idx & 15) * 4;        // n offset within tile
            int4 v = *(const int4*)(w + (size_t)(k0 + kk) * N_DIM + n0 + nw);
            tile[nw + 0][kk] = __int2half_rn(v.x);
            tile[nw + 1][kk] = __int2half_rn(v.y);
            tile[nw + 2][kk] = __int2half_rn(v.z);
            tile[nw + 3][kk] = __int2half_rn(v.w);
        }
        __syncthreads();
#pragma unroll
        for (int c = 0; c < 2; c++) {
            int idx = t + 256 * c;          // 64 rows x 8 chunks of 8 halves
            int nn = idx >> 3;
            int kc = (idx & 7) * 8;
            uint4 v = *(uint4*)&tile[nn][kc];
            *(uint4*)(g_Bth + (size_t)(n0 + nn) * K_DIM + k0 + kc) = v;
        }
    }
}

// ---------------- GEMM: fp16 HMMA + fused dequant ----------------
__global__ __launch_bounds__(NTHREADS, 2)
void gemm_kernel(const float* __restrict__ wscale, const float* __restrict__ iscale,
                 float* __restrict__ out) {
    extern __shared__ char smem[];
    const uint32_t sb = smem_u32(smem);
    const int tid = threadIdx.x;
    const int wid = tid >> 5;
    const int lane = tid & 31;
    const int warp_m = wid & 1;         // 2 warp rows (64 m each)
    const int warp_n = wid >> 1;        // 4 warp cols (32 n each)

    // rasterization: GROUP m-tiles sweep N together for L2 reuse of the A band
    const int NT = N_DIM / BN;          // 86
    const int GROUP = 16;
    int pid = blockIdx.x;
    int width = GROUP * NT;
    int group = pid / width;
    int rem = pid - group * width;
    int mt_idx = group * GROUP + (rem % GROUP);
    int nt_idx = rem / GROUP;
    const int m0 = mt_idx * BM;
    const int n0 = nt_idx * BN;

    // --------- precomputed cp.async addressing (kt-invariant parts) ---------
    const int ld_row = tid >> 3;         // 0..31
    const int ld_c   = tid & 7;          // 16B chunk
    const uint32_t ld_sw = (uint32_t)((ld_c ^ (ld_row & 7)) << 4);
    const uint32_t dst0 = (uint32_t)ld_row * ROW_BYTES + ld_sw;
    const char* a_src0 = ((const char*)g_Ah)  + ((size_t)(m0 + ld_row) * K_DIM) * 2 + ld_c * 16;
    const char* b_src0 = ((const char*)g_Bth) + ((size_t)(n0 + ld_row) * K_DIM) * 2 + ld_c * 16;
    const size_t row_step = (size_t)32 * K_DIM * 2;   // +32 rows

#define ISSUE_TILE(s, kt)                                                          \
    do {                                                                           \
        const uint32_t a_sti = sb + (s) * STAGE_BYTES;                             \
        const uint32_t b_sti = a_sti + A_STAGE_BYTES;                              \
        const char* a_p = a_src0 + (size_t)(kt) * ROW_BYTES;                       \
        const char* b_p = b_src0 + (size_t)(kt) * ROW_BYTES;                       \
        _Pragma("unroll")                                                          \
        for (int i = 0; i < 4; i++) {                                              \
            cp_async16(a_sti + dst0 + i * (32 * ROW_BYTES), a_p + i * row_step);   \
            cp_async16(b_sti + dst0 + i * (32 * ROW_BYTES), b_p + i * row_step);   \
        }                                                                          \
    } while (0)

    float acc[4][4][4];
#pragma unroll
    for (int i = 0; i < 4; i++)
#pragma unroll
        for (int j = 0; j < 4; j++)
#pragma unroll
            for (int k = 0; k < 4; k++) acc[i][j][k] = 0.0f;

    // prologue: stages 0,1 in flight
    ISSUE_TILE(0, 0); CP_COMMIT();
    ISSUE_TILE(1, 1); CP_COMMIT();

    // ldmatrix per-lane addressing (PTX m16n8k16 fragment tables)
    const int lw = lane & 7;
    const uint32_t a_row_off = (uint32_t)(warp_m * 64 + (lane & 15)) * ROW_BYTES;
    const uint32_t b_row_off = (uint32_t)(warp_n * 32 + ((lane >> 4) << 3) + (lane & 7)) * ROW_BYTES;
    const int a_hi = lane >> 4;          // 0..1
    const int b_hi = (lane >> 3) & 1;    // 0..1
    uint32_t a_ck[4], b_ck[4];
#pragma unroll
    for (int ks = 0; ks < 4; ks++) {
        a_ck[ks] = (uint32_t)(((2 * ks + a_hi) ^ lw) << 4);
        b_ck[ks] = (uint32_t)(((2 * ks + b_hi) ^ lw) << 4);
    }

#pragma unroll 12
    for (int kt = 0; kt < KTILES; kt++) {
        CP_WAIT(1);
        __syncthreads();

        const int s = kt % STAGES;
        const uint32_t a_st = sb + s * STAGE_BYTES;
        const uint32_t b_st = a_st + A_STAGE_BYTES;

        // software-pipelined fragment loads; cp.async burst issued after the
        // ks=0 mma block so the tensor pipe refills immediately post-barrier.
        uint32_t af[2][4][4], bf[2][2][4];
#pragma unroll
        for (int mt = 0; mt < 4; mt++)
            LDMX4(af[0][mt], a_st + a_row_off + (uint32_t)(mt * 16) * ROW_BYTES + a_ck[0]);
#pragma unroll
        for (int nq = 0; nq < 2; nq++)
            LDMX4(bf[0][nq], b_st + b_row_off + (uint32_t)(nq * 16) * ROW_BYTES + b_ck[0]);

#pragma unroll
        for (int ks = 0; ks < 4; ks++) {   // four k16 slices per BK=64
            const int cur = ks & 1, nxt = cur ^ 1;
            if (ks < 3) {
#pragma unroll
                for (int mt = 0; mt < 4; mt++)
                    LDMX4(af[nxt][mt], a_st + a_row_off + (uint32_t)(mt * 16) * ROW_BYTES + a_ck[ks + 1]);
#pragma unroll
                for (int nq = 0; nq < 2; nq++)
                    LDMX4(bf[nxt][nq], b_st + b_row_off + (uint32_t)(nq * 16) * ROW_BYTES + b_ck[ks + 1]);
            }
#pragma unroll
            for (int mt = 0; mt < 4; mt++)
#pragma unroll
                for (int nt = 0; nt < 4; nt++)
                    MMA_F16(acc[mt][nt], af[cur][mt],
                            bf[cur][nt >> 1][(nt & 1) * 2], bf[cur][nt >> 1][(nt & 1) * 2 + 1]);
            if (ks == 0) {
                // Overwrites stage (kt+2)%3 == (kt-1)%3: all warps finished
                // computing kt-1 before this kt's barrier, so it is safe.
                if (kt + 2 < KTILES) ISSUE_TILE((kt + 2) % STAGES, kt + 2);
                CP_COMMIT();   // unconditional: empty commit groups are legal
            }
        }
    }

    // ---- epilogue: fused dequant, fp32 stores ----
    const float sin = __ldg(iscale);
    const int m_base_g = m0 + warp_m * 64;
    const int n_base_g = n0 + warp_n * 32;
#pragma unroll
    for (int nt = 0; nt < 4; nt++) {
        const int n = n_base_g + nt * 8 + 2 * (lane & 3);
        const float w0 = sin * __ldg(wscale + n);
        const float w1 = sin * __ldg(wscale + n + 1);
#pragma unroll
        for (int mt = 0; mt < 4; mt++) {
            const int r0 = m_base_g + mt * 16 + (lane >> 2);
            float2 v0, v1;
            v0.x = acc[mt][nt][0] * w0;
            v0.y = acc[mt][nt][1] * w1;
            v1.x = acc[mt][nt][2] * w0;
            v1.y = acc[mt][nt][3] * w1;
            *(float2*)(out + (size_t)r0 * N_DIM + n) = v0;
            *(float2*)(out + (size_t)(r0 + 8) * N_DIM + n) = v1;
        }
    }
#undef ISSUE_TILE
}

// ---------------- launch ----------------
extern "C" void kernel_launch(void* const* d_in, const int* in_sizes, int n_in,
                              void* d_out, int out_size) {
    (void)out_size;
    // Inputs identified by element count; qweight arrives as int32.
    const float* x  = nullptr;
    const int*   w  = nullptr;
    const float* ws = nullptr;
    const float* is = nullptr;
    const long long XE = (long long)M_DIM * K_DIM;
    const long long WE = (long long)K_DIM * N_DIM;
    for (int i = 0; i < n_in; i++) {
        long long sz = in_sizes[i];
        if (sz == XE)           x  = (const float*)d_in[i];
        else if (sz == WE)      w  = (const int*)d_in[i];
        else if (sz == N_DIM)   ws = (const float*)d_in[i];
        else if (sz == 1)       is = (const float*)d_in[i];
    }
    if (!x)  x  = (const float*)d_in[0];
    if (!w)  w  = (const int*)d_in[1];
    if (!ws) ws = (const float*)d_in[2];
    if (!is) is = (const float*)d_in[3];
    float* out = (float*)d_out;

    // 1) fused pre-pass: quant (x) + transpose/narrow (W), run concurrently
    prep_kernel<<<QBLOCKS + TBLOCKS, 256>>>(x, w, is);

    // 2) fp16 tensor-core GEMM + fused dequant (2 CTAs/SM)
    cudaFuncSetAttribute(gemm_kernel, cudaFuncAttributeMaxDynamicSharedMemorySize, SMEM_BYTES);
    gemm_kernel<<<(M_DIM / BM) * (N_DIM / BN), NTHREADS, SMEM_BYTES>>>(ws, is, out);
}